// round 5
// baseline (speedup 1.0000x reference)
#include <cuda_runtime.h>
#include <cuda_bf16.h>
#include <cstdint>

// ---------------------------------------------------------------------------
#define Mn  16384
#define Nn  8192
#define Kn  256
#define HWn 1024
#define Bln 16

#define OUT_ZQ  (Mn * Kn)
#define OUT_IDX (2 * Mn * Kn)

#define CERT_WINDOW 3.5f   // > 2x realistic int8-dot error bound

// ---------------------------------------------------------------------------
// Device scratch (allocation-free contract)
// ---------------------------------------------------------------------------
__device__ __align__(16) int8_t g_qz[Mn * Kn];
__device__ __align__(16) int8_t g_qw[Nn * Kn];
__device__ float g_izs[Mn];        // inverse z scale  (max|z|/127)
__device__ float g_iws[Nn];        // inverse w scale
__device__ float g_wnorm[Nn];      // 0.5*||w||^2 (fp32 exact)
__device__ int   g_bestidx[Mn];
__device__ int   g_cand[Mn][6];
__device__ int   g_flag[Mn];
__device__ int   g_flag_list[Mn];
__device__ int   g_flag_count;

// ---------------------------------------------------------------------------
__device__ __forceinline__ uint32_t smem_u32(const void* p) {
    uint32_t a;
    asm("{ .reg .u64 t; cvta.to.shared.u64 t, %1; cvt.u32.u64 %0, t; }"
        : "=r"(a) : "l"(p));
    return a;
}
__device__ __forceinline__ void cp_async16(uint32_t dst, const void* src) {
    asm volatile("cp.async.cg.shared.global [%0], [%1], 16;"
                 :: "r"(dst), "l"(src) : "memory");
}
#define CP_COMMIT() asm volatile("cp.async.commit_group;" ::: "memory")
#define CP_WAIT0()  asm volatile("cp.async.wait_group 0;" ::: "memory")

// non-transposed ldmatrix on byte data: 8 rows x 16B per matrix; lane L of a
// matrix receives the 4 bytes at (row L/4, byteoff (L%4)*4) -> exactly the s8
// IMMA fragment quads for row-major [m][k] (A) and [n][k] (B).
#define LDSM_X4(r0, r1, r2, r3, a) \
    asm volatile("ldmatrix.sync.aligned.m8n8.x4.shared.b16 {%0,%1,%2,%3}, [%4];" \
                 : "=r"(r0), "=r"(r1), "=r"(r2), "=r"(r3) : "r"(a))

#define IMMA16832(c, a, b) \
    asm volatile("mma.sync.aligned.m16n8k32.row.col.s32.s8.s8.s32 " \
                 "{%0,%1,%2,%3}, {%4,%5,%6,%7}, {%8,%9}, {%0,%1,%2,%3};" \
                 : "+r"((c)[0]), "+r"((c)[1]), "+r"((c)[2]), "+r"((c)[3]) \
                 : "r"((a)[0]), "r"((a)[1]), "r"((a)[2]), "r"((a)[3]), \
                   "r"((b)[0]), "r"((b)[1]))

// ---------------------------------------------------------------------------
// 1) Transpose: z [B,C,HW] -> z_out fp32 [B,HW,C]
// ---------------------------------------------------------------------------
__global__ void transpose_kernel(const float* __restrict__ z,
                                 float* __restrict__ zout) {
    __shared__ float tile[32][33];
    int b   = blockIdx.z;
    int hw0 = blockIdx.x * 32;
    int c0  = blockIdx.y * 32;
    const float* zp = z + (size_t)b * (Kn * HWn);
    size_t obase    = (size_t)b * (Kn * HWn);
    int tx = threadIdx.x, ty = threadIdx.y;
#pragma unroll
    for (int j = 0; j < 32; j += 8)
        tile[ty + j][tx] = zp[(c0 + ty + j) * HWn + hw0 + tx];
    __syncthreads();
#pragma unroll
    for (int j = 0; j < 32; j += 8)
        zout[obase + (size_t)(hw0 + ty + j) * Kn + c0 + tx] = tile[tx][ty + j];
}

// ---------------------------------------------------------------------------
// 2a) z row quantization: one warp per row
// ---------------------------------------------------------------------------
__global__ __launch_bounds__(256) void zquant_kernel(const float* __restrict__ zout) {
    int row  = (blockIdx.x * blockDim.x + threadIdx.x) >> 5;
    int lane = threadIdx.x & 31;
    const float4* zp = (const float4*)(zout + (size_t)row * Kn) + lane * 2;
    float4 v0 = zp[0], v1 = zp[1];
    float vals[8] = {v0.x, v0.y, v0.z, v0.w, v1.x, v1.y, v1.z, v1.w};
    float mx = 0.f;
#pragma unroll
    for (int j = 0; j < 8; j++) mx = fmaxf(mx, fabsf(vals[j]));
#pragma unroll
    for (int o = 16; o > 0; o >>= 1) mx = fmaxf(mx, __shfl_xor_sync(0xffffffffu, mx, o));
    mx = fmaxf(mx, 1e-20f);
    float zs = 127.f / mx;
    uint32_t p0 = 0, p1 = 0;
#pragma unroll
    for (int j = 0; j < 4; j++) {
        p0 |= ((uint32_t)(__float2int_rn(vals[j] * zs)     & 0xff)) << (8 * j);
        p1 |= ((uint32_t)(__float2int_rn(vals[4 + j] * zs) & 0xff)) << (8 * j);
    }
    *(uint2*)(g_qz + (size_t)row * Kn + lane * 8) = make_uint2(p0, p1);
    if (lane == 0) g_izs[row] = mx / 127.f;
}

// ---------------------------------------------------------------------------
// 2b) w row quantization + wnorm
// ---------------------------------------------------------------------------
__global__ __launch_bounds__(256) void wquant_kernel(const float* __restrict__ w) {
    if (blockIdx.x == 0 && threadIdx.x == 0) g_flag_count = 0;
    int row  = (blockIdx.x * blockDim.x + threadIdx.x) >> 5;
    int lane = threadIdx.x & 31;
    if (row >= Nn) return;
    const float4* wp = (const float4*)(w + (size_t)row * Kn) + lane * 2;
    float4 v0 = wp[0], v1 = wp[1];
    float vals[8] = {v0.x, v0.y, v0.z, v0.w, v1.x, v1.y, v1.z, v1.w};
    float mx = 0.f, ss = 0.f;
#pragma unroll
    for (int j = 0; j < 8; j++) { mx = fmaxf(mx, fabsf(vals[j])); ss += vals[j] * vals[j]; }
#pragma unroll
    for (int o = 16; o > 0; o >>= 1) {
        mx = fmaxf(mx, __shfl_xor_sync(0xffffffffu, mx, o));
        ss += __shfl_xor_sync(0xffffffffu, ss, o);
    }
    mx = fmaxf(mx, 1e-20f);
    float ws = 127.f / mx;
    uint32_t p0 = 0, p1 = 0;
#pragma unroll
    for (int j = 0; j < 4; j++) {
        p0 |= ((uint32_t)(__float2int_rn(vals[j] * ws)     & 0xff)) << (8 * j);
        p1 |= ((uint32_t)(__float2int_rn(vals[4 + j] * ws) & 0xff)) << (8 * j);
    }
    *(uint2*)(g_qw + (size_t)row * Kn + lane * 8) = make_uint2(p0, p1);
    if (lane == 0) {
        g_iws[row]   = mx / 127.f;
        g_wnorm[row] = 0.5f * ss;
    }
}

// ---------------------------------------------------------------------------
// 3) int8 IMMA GEMM + per-row top-6
//    BM=128/CTA, 8 warps 4(m)x2(n), warp tile 32x64, K=256 (8 ksteps of 32)
// ---------------------------------------------------------------------------
#define SM_A    0          // 32 KB
#define SM_B0   32768      // 32 KB
#define SM_B1   65536      // 32 KB
#define SM_WN   98304      // 32 KB  (0.5||w||^2 fp32)
#define SM_IWS  131072     // 32 KB  (inv w scale fp32)
#define SM_IZS  163840     // 512 B
#define SMEM_BYTES 164352
#define SM_MV   0          // merge (post-loop, whole smem free)
#define SM_MI   24576

// swizzled byte offset: 256B rows, 16B chunk c (0..15), row m
#define ROWSWZ(m, c) ((uint32_t)((m) * 256 + ((((c) & 8) | (((c) ^ ((m) & 7)) & 7)) << 4)))

__global__ void __launch_bounds__(256, 1) gemm_kernel() {
    extern __shared__ char smem[];
    const uint32_t sbase = smem_u32(smem);
    const int tid  = threadIdx.x;
    const int lane = tid & 31;
    const int wid  = tid >> 5;
    const int wm   = wid >> 1;
    const int wn   = wid & 1;
    const int lj   = lane >> 3;
    const int lr   = lane & 7;
    const int m0   = blockIdx.x * 128;

    float* swn  = (float*)(smem + SM_WN);
    float* siws = (float*)(smem + SM_IWS);
    float* sizs = (float*)(smem + SM_IZS);
    for (int i = tid; i < Nn; i += 256) { swn[i] = g_wnorm[i]; siws[i] = g_iws[i]; }
    if (tid < 128) sizs[tid] = g_izs[m0 + tid];

    // A tile (128 x 256 s8)
    {
        const char* src = (const char*)g_qz + (size_t)m0 * 256;
#pragma unroll
        for (int i = 0; i < 8; i++) {
            int f = tid + i * 256;
            int m = f >> 4, c = f & 15;
            cp_async16(sbase + SM_A + ROWSWZ(m, c), src + (size_t)m * 256 + c * 16);
        }
    }
    // B tile 0
    {
        const char* src = (const char*)g_qw;
#pragma unroll
        for (int i = 0; i < 8; i++) {
            int f = tid + i * 256;
            int n = f >> 4, c = f & 15;
            cp_async16(sbase + SM_B0 + ROWSWZ(n, c), src + (size_t)n * 256 + c * 16);
        }
    }
    CP_COMMIT();
    CP_WAIT0();
    __syncthreads();

    // per-slot inv z scales (slot s = mt*2 + half; row = wm*32+(s>>1)*16+(s&1)*8+(lane>>2))
    float izv[4];
#pragma unroll
    for (int s = 0; s < 4; s++)
        izv[s] = sizs[wm * 32 + (s >> 1) * 16 + (s & 1) * 8 + (lane >> 2)];

    uint32_t aBase[2], aSwz[2];
#pragma unroll
    for (int mt = 0; mt < 2; mt++) {
        int ml = wm * 32 + mt * 16 + ((lj & 1) << 3) + lr;
        aBase[mt] = sbase + SM_A + (uint32_t)ml * 256;
        aSwz[mt]  = (uint32_t)(ml & 7);
    }
    uint32_t bBase[4], bSwz[4];
#pragma unroll
    for (int p = 0; p < 4; p++) {
        int nl = wn * 64 + p * 16 + ((lj >> 1) << 3) + lr;
        bBase[p] = (uint32_t)nl * 256;
        bSwz[p]  = (uint32_t)(nl & 7);
    }

    float bv[4][6];
    int   bi[4][6];
#pragma unroll
    for (int s = 0; s < 4; s++)
#pragma unroll
        for (int e = 0; e < 6; e++) { bv[s][e] = -3.4e38f; bi[s][e] = 0; }

#define TOP6_INS(S, VAL, IDX)                                              \
    if ((VAL) > bv[S][5]) {                                                \
        float _cv = (VAL); int _ci = (IDX);                                \
        _Pragma("unroll")                                                  \
        for (int _q = 0; _q < 6; _q++) {                                   \
            if (_cv > bv[S][_q]) {                                         \
                float _tv = bv[S][_q]; int _ti = bi[S][_q];                \
                bv[S][_q] = _cv; bi[S][_q] = _ci; _cv = _tv; _ci = _ti;    \
            }                                                              \
        }                                                                  \
    }

    int buf = 0;
    for (int t = 0; t < 64; t++) {
        const uint32_t cur = sbase + (buf ? SM_B1 : SM_B0);
        if (t < 63) {
            const uint32_t nxt = sbase + (buf ? SM_B0 : SM_B1);
            const char* src = (const char*)g_qw + (size_t)(t + 1) * 128 * 256;
#pragma unroll
            for (int i = 0; i < 8; i++) {
                int f = tid + i * 256;
                int n = f >> 4, c = f & 15;
                cp_async16(nxt + ROWSWZ(n, c), src + (size_t)n * 256 + c * 16);
            }
            CP_COMMIT();
        }

        int C[2][8][4];
#pragma unroll
        for (int mt = 0; mt < 2; mt++)
#pragma unroll
            for (int f = 0; f < 8; f++)
#pragma unroll
                for (int e = 0; e < 4; e++) C[mt][f][e] = 0;

#pragma unroll
        for (int ks = 0; ks < 8; ks++) {
            uint32_t a[2][4];
#pragma unroll
            for (int mt = 0; mt < 2; mt++) {
                uint32_t cA = (uint32_t)(ks * 2 + (lj >> 1));
                uint32_t ad = aBase[mt] + ((((cA & 8) | ((cA ^ aSwz[mt]) & 7))) << 4);
                LDSM_X4(a[mt][0], a[mt][1], a[mt][2], a[mt][3], ad);
            }
            uint32_t b[8][2];
#pragma unroll
            for (int p = 0; p < 4; p++) {
                uint32_t cB = (uint32_t)(ks * 2 + (lj & 1));
                uint32_t bd = cur + bBase[p] + ((((cB & 8) | ((cB ^ bSwz[p]) & 7))) << 4);
                LDSM_X4(b[2 * p][0], b[2 * p][1], b[2 * p + 1][0], b[2 * p + 1][1], bd);
            }
#pragma unroll
            for (int mt = 0; mt < 2; mt++)
#pragma unroll
                for (int f = 0; f < 8; f++)
                    IMMA16832(C[mt][f], a[mt], b[f]);
        }

        // epilogue: s = izs * (Q * iws) - 0.5||w||^2 ; update top-6
        {
            int cbase = t * 128 + wn * 64 + 2 * (lane & 3);
#pragma unroll
            for (int f = 0; f < 8; f++) {
#pragma unroll
                for (int e = 0; e < 2; e++) {
                    int col = cbase + f * 8 + e;
                    float iw = siws[col];
                    float wv = swn[col];
#pragma unroll
                    for (int mt = 0; mt < 2; mt++) {
                        float s0 = __int2float_rn(C[mt][f][e])     * iw * izv[mt * 2 + 0] - wv;
                        float s1 = __int2float_rn(C[mt][f][2 + e]) * iw * izv[mt * 2 + 1] - wv;
                        TOP6_INS(mt * 2 + 0, s0, col);
                        TOP6_INS(mt * 2 + 1, s1, col);
                    }
                }
            }
        }

        if (t < 63) CP_WAIT0();
        __syncthreads();
        buf ^= 1;
    }

    // ---- cross-thread merge (after final sync, all smem free) ----
    float* MV = (float*)(smem + SM_MV);   // [128][48]
    int*   MI = (int*)  (smem + SM_MI);   // [128][48]
#pragma unroll
    for (int s = 0; s < 4; s++) {
        int row = wm * 32 + (s >> 1) * 16 + (s & 1) * 8 + (lane >> 2);
        int col = wn * 24 + (lane & 3) * 6;
#pragma unroll
        for (int e = 0; e < 6; e++) {
            MV[row * 48 + col + e] = bv[s][e];
            MI[row * 48 + col + e] = bi[s][e];
        }
    }
    __syncthreads();

    if (tid < 128) {
        int row = tid;
        float tv[6] = {-3.4e38f, -3.4e38f, -3.4e38f, -3.4e38f, -3.4e38f, -3.4e38f};
        int   ti[6] = {0, 0, 0, 0, 0, 0};
#pragma unroll 8
        for (int k = 0; k < 48; k++) {
            float v  = MV[row * 48 + k];
            int   ix = MI[row * 48 + k];
            if (v > tv[5]) {
                float cv = v; int ci = ix;
#pragma unroll
                for (int q = 0; q < 6; q++) {
                    if (cv > tv[q]) {
                        float xv = tv[q]; int xi = ti[q];
                        tv[q] = cv; ti[q] = ci; cv = xv; ci = xi;
                    }
                }
            }
        }
        int m = m0 + row;
#pragma unroll
        for (int e = 0; e < 6; e++) g_cand[m][e] = ti[e];
        int fl = (tv[0] - tv[5] <= CERT_WINDOW) ? 1 : 0;
        g_flag[m] = fl;
        if (fl) {
            int p = atomicAdd(&g_flag_count, 1);
            g_flag_list[p] = m;
        }
    }
}

// ---------------------------------------------------------------------------
// 4) Exact fp32 rescore of top-6 candidates (one warp per row)
// ---------------------------------------------------------------------------
__global__ __launch_bounds__(256) void rescore_kernel(const float* __restrict__ zout,
                                                      const float* __restrict__ w,
                                                      float* __restrict__ idxf) {
    int m    = (blockIdx.x * blockDim.x + threadIdx.x) >> 5;
    int lane = threadIdx.x & 31;
    if (m >= Mn) return;
    if (g_flag[m]) return;

    float zr[8];
    const float* zp = zout + (size_t)m * Kn;
#pragma unroll
    for (int j = 0; j < 8; j++) zr[j] = zp[lane + 32 * j];

    float bestS = -3.4e38f;
    int   bestI = 0x7fffffff;
#pragma unroll
    for (int c = 0; c < 6; c++) {
        int idx = g_cand[m][c];
        const float* wp = w + (size_t)idx * Kn;
        float s = 0.f;
#pragma unroll
        for (int j = 0; j < 8; j++) s += zr[j] * wp[lane + 32 * j];
#pragma unroll
        for (int o = 16; o > 0; o >>= 1) s += __shfl_xor_sync(0xffffffffu, s, o);
        s -= g_wnorm[idx];
        if (s > bestS || (s == bestS && idx < bestI)) { bestS = s; bestI = idx; }
    }
    if (lane == 0) {
        g_bestidx[m] = bestI;
        idxf[m] = (float)bestI;
    }
}

// ---------------------------------------------------------------------------
// 5) Fallback full exact scan for flagged rows
// ---------------------------------------------------------------------------
__global__ __launch_bounds__(256) void fallback_kernel(const float* __restrict__ zout,
                                                       const float* __restrict__ w,
                                                       float* __restrict__ idxf) {
    __shared__ float sv[8];
    __shared__ int   si[8];
    int nflag = g_flag_count;
    int wi = threadIdx.x >> 5, lane = threadIdx.x & 31;
    for (int r = blockIdx.x; r < nflag; r += gridDim.x) {
        int m = g_flag_list[r];
        float zr[8];
        const float* zp = zout + (size_t)m * Kn;
#pragma unroll
        for (int j = 0; j < 8; j++) zr[j] = zp[lane + 32 * j];
        float bS = -3.4e38f;
        int   bI = 0x7fffffff;
        for (int n = wi; n < Nn; n += 8) {
            const float* wp = w + (size_t)n * Kn;
            float s = 0.f;
#pragma unroll
            for (int j = 0; j < 8; j++) s += zr[j] * wp[lane + 32 * j];
#pragma unroll
            for (int o = 16; o > 0; o >>= 1) s += __shfl_xor_sync(0xffffffffu, s, o);
            s -= g_wnorm[n];
            if (s > bS || (s == bS && n < bI)) { bS = s; bI = n; }
        }
        if (lane == 0) { sv[wi] = bS; si[wi] = bI; }
        __syncthreads();
        if (threadIdx.x == 0) {
            float bvv = sv[0]; int bii = si[0];
#pragma unroll
            for (int q = 1; q < 8; q++) {
                if (sv[q] > bvv || (sv[q] == bvv && si[q] < bii)) { bvv = sv[q]; bii = si[q]; }
            }
            g_bestidx[m] = bii;
            idxf[m] = (float)bii;
        }
        __syncthreads();
    }
}

// ---------------------------------------------------------------------------
// 6) Gather z_q
// ---------------------------------------------------------------------------
__global__ void gather_kernel(const float* __restrict__ w,
                              float* __restrict__ zq) {
    int t   = blockIdx.x * blockDim.x + threadIdx.x;
    int row = t >> 6;
    int c   = t & 63;
    int idx = g_bestidx[row];
    reinterpret_cast<float4*>(zq)[t] =
        reinterpret_cast<const float4*>(w)[(size_t)idx * 64 + c];
}

// ---------------------------------------------------------------------------
extern "C" void kernel_launch(void* const* d_in, const int* in_sizes, int n_in,
                              void* d_out, int out_size) {
    const float* z = (const float*)d_in[0];
    const float* w = (const float*)d_in[1];
    float* out   = (float*)d_out;
    float* z_out = out;
    float* z_q   = out + OUT_ZQ;
    float* idxf  = out + OUT_IDX;

    cudaFuncSetAttribute(gemm_kernel,
                         cudaFuncAttributeMaxDynamicSharedMemorySize, SMEM_BYTES);

    dim3 tt(32, 8);
    transpose_kernel<<<dim3(HWn / 32, Kn / 32, Bln), tt>>>(z, z_out);
    zquant_kernel<<<Mn / 8, 256>>>(z_out);
    wquant_kernel<<<Nn / 8, 256>>>(w);
    gemm_kernel<<<Mn / 128, 256, SMEM_BYTES>>>();
    rescore_kernel<<<Mn / 8, 256>>>(z_out, w, idxf);
    fallback_kernel<<<128, 256>>>(z_out, w, idxf);
    gather_kernel<<<(Mn * Kn / 4) / 256, 256>>>(w, z_q);
}

// round 6
// speedup vs baseline: 3.7211x; 3.7211x over previous
#include <cuda_runtime.h>
#include <cuda_bf16.h>
#include <cstdint>

// ---------------------------------------------------------------------------
#define Mn  16384
#define Nn  8192
#define Kn  256
#define HWn 1024
#define Bln 16

#define OUT_ZQ  (Mn * Kn)
#define OUT_IDX (2 * Mn * Kn)

#define CERT_WINDOW 3.5f   // on v0 - v15 of the merged 16-candidate pool
#define NCAND 16

// ---------------------------------------------------------------------------
__device__ __align__(16) int8_t g_qz[Mn * Kn];
__device__ __align__(16) int8_t g_qw[Nn * Kn];
__device__ float g_izs[Mn];
__device__ float g_iws[Nn];
__device__ float g_wnorm[Nn];
__device__ int   g_bestidx[Mn];
__device__ int   g_cand[Mn][NCAND];
__device__ int   g_flag[Mn];
__device__ int   g_flag_list[Mn];
__device__ int   g_flag_count;

// ---------------------------------------------------------------------------
__device__ __forceinline__ uint32_t smem_u32(const void* p) {
    uint32_t a;
    asm("{ .reg .u64 t; cvta.to.shared.u64 t, %1; cvt.u32.u64 %0, t; }"
        : "=r"(a) : "l"(p));
    return a;
}
__device__ __forceinline__ void cp_async16(uint32_t dst, const void* src) {
    asm volatile("cp.async.cg.shared.global [%0], [%1], 16;"
                 :: "r"(dst), "l"(src) : "memory");
}
#define CP_COMMIT() asm volatile("cp.async.commit_group;" ::: "memory")
#define CP_WAIT0()  asm volatile("cp.async.wait_group 0;" ::: "memory")

#define LDSM_X4(r0, r1, r2, r3, a) \
    asm volatile("ldmatrix.sync.aligned.m8n8.x4.shared.b16 {%0,%1,%2,%3}, [%4];" \
                 : "=r"(r0), "=r"(r1), "=r"(r2), "=r"(r3) : "r"(a))

#define IMMA16832(c, a, b) \
    asm volatile("mma.sync.aligned.m16n8k32.row.col.s32.s8.s8.s32 " \
                 "{%0,%1,%2,%3}, {%4,%5,%6,%7}, {%8,%9}, {%0,%1,%2,%3};" \
                 : "+r"((c)[0]), "+r"((c)[1]), "+r"((c)[2]), "+r"((c)[3]) \
                 : "r"((a)[0]), "r"((a)[1]), "r"((a)[2]), "r"((a)[3]), \
                   "r"((b)[0]), "r"((b)[1]))

// ---------------------------------------------------------------------------
// 1) Transpose: z [B,C,HW] -> z_out fp32 [B,HW,C]
// ---------------------------------------------------------------------------
__global__ void transpose_kernel(const float* __restrict__ z,
                                 float* __restrict__ zout) {
    __shared__ float tile[32][33];
    int b   = blockIdx.z;
    int hw0 = blockIdx.x * 32;
    int c0  = blockIdx.y * 32;
    const float* zp = z + (size_t)b * (Kn * HWn);
    size_t obase    = (size_t)b * (Kn * HWn);
    int tx = threadIdx.x, ty = threadIdx.y;
#pragma unroll
    for (int j = 0; j < 32; j += 8)
        tile[ty + j][tx] = zp[(c0 + ty + j) * HWn + hw0 + tx];
    __syncthreads();
#pragma unroll
    for (int j = 0; j < 32; j += 8)
        zout[obase + (size_t)(hw0 + ty + j) * Kn + c0 + tx] = tile[tx][ty + j];
}

// ---------------------------------------------------------------------------
// 2a) z row quantization
// ---------------------------------------------------------------------------
__global__ __launch_bounds__(256) void zquant_kernel(const float* __restrict__ zout) {
    int row  = (blockIdx.x * blockDim.x + threadIdx.x) >> 5;
    int lane = threadIdx.x & 31;
    const float4* zp = (const float4*)(zout + (size_t)row * Kn) + lane * 2;
    float4 v0 = zp[0], v1 = zp[1];
    float vals[8] = {v0.x, v0.y, v0.z, v0.w, v1.x, v1.y, v1.z, v1.w};
    float mx = 0.f;
#pragma unroll
    for (int j = 0; j < 8; j++) mx = fmaxf(mx, fabsf(vals[j]));
#pragma unroll
    for (int o = 16; o > 0; o >>= 1) mx = fmaxf(mx, __shfl_xor_sync(0xffffffffu, mx, o));
    mx = fmaxf(mx, 1e-20f);
    float zs = 127.f / mx;
    uint32_t p0 = 0, p1 = 0;
#pragma unroll
    for (int j = 0; j < 4; j++) {
        p0 |= ((uint32_t)(__float2int_rn(vals[j] * zs)     & 0xff)) << (8 * j);
        p1 |= ((uint32_t)(__float2int_rn(vals[4 + j] * zs) & 0xff)) << (8 * j);
    }
    *(uint2*)(g_qz + (size_t)row * Kn + lane * 8) = make_uint2(p0, p1);
    if (lane == 0) g_izs[row] = mx / 127.f;
}

// ---------------------------------------------------------------------------
// 2b) w row quantization + wnorm
// ---------------------------------------------------------------------------
__global__ __launch_bounds__(256) void wquant_kernel(const float* __restrict__ w) {
    if (blockIdx.x == 0 && threadIdx.x == 0) g_flag_count = 0;
    int row  = (blockIdx.x * blockDim.x + threadIdx.x) >> 5;
    int lane = threadIdx.x & 31;
    if (row >= Nn) return;
    const float4* wp = (const float4*)(w + (size_t)row * Kn) + lane * 2;
    float4 v0 = wp[0], v1 = wp[1];
    float vals[8] = {v0.x, v0.y, v0.z, v0.w, v1.x, v1.y, v1.z, v1.w};
    float mx = 0.f, ss = 0.f;
#pragma unroll
    for (int j = 0; j < 8; j++) { mx = fmaxf(mx, fabsf(vals[j])); ss += vals[j] * vals[j]; }
#pragma unroll
    for (int o = 16; o > 0; o >>= 1) {
        mx = fmaxf(mx, __shfl_xor_sync(0xffffffffu, mx, o));
        ss += __shfl_xor_sync(0xffffffffu, ss, o);
    }
    mx = fmaxf(mx, 1e-20f);
    float ws = 127.f / mx;
    uint32_t p0 = 0, p1 = 0;
#pragma unroll
    for (int j = 0; j < 4; j++) {
        p0 |= ((uint32_t)(__float2int_rn(vals[j] * ws)     & 0xff)) << (8 * j);
        p1 |= ((uint32_t)(__float2int_rn(vals[4 + j] * ws) & 0xff)) << (8 * j);
    }
    *(uint2*)(g_qw + (size_t)row * Kn + lane * 8) = make_uint2(p0, p1);
    if (lane == 0) {
        g_iws[row]   = mx / 127.f;
        g_wnorm[row] = 0.5f * ss;
    }
}

// ---------------------------------------------------------------------------
// 3) int8 IMMA GEMM + per-row top-6 -> merged top-16
// ---------------------------------------------------------------------------
#define SM_A    0
#define SM_B0   32768
#define SM_B1   65536
#define SM_WN   98304
#define SM_IWS  131072
#define SM_IZS  163840
#define SMEM_BYTES 164352
#define SM_MV   0
#define SM_MI   24576

#define ROWSWZ(m, c) ((uint32_t)((m) * 256 + ((((c) & 8) | (((c) ^ ((m) & 7)) & 7)) << 4)))

__global__ void __launch_bounds__(256, 1) gemm_kernel() {
    extern __shared__ char smem[];
    const uint32_t sbase = smem_u32(smem);
    const int tid  = threadIdx.x;
    const int lane = tid & 31;
    const int wid  = tid >> 5;
    const int wm   = wid >> 1;
    const int wn   = wid & 1;
    const int lj   = lane >> 3;
    const int lr   = lane & 7;
    const int m0   = blockIdx.x * 128;

    float* swn  = (float*)(smem + SM_WN);
    float* siws = (float*)(smem + SM_IWS);
    float* sizs = (float*)(smem + SM_IZS);
    for (int i = tid; i < Nn; i += 256) { swn[i] = g_wnorm[i]; siws[i] = g_iws[i]; }
    if (tid < 128) sizs[tid] = g_izs[m0 + tid];

    {
        const char* src = (const char*)g_qz + (size_t)m0 * 256;
#pragma unroll
        for (int i = 0; i < 8; i++) {
            int f = tid + i * 256;
            int m = f >> 4, c = f & 15;
            cp_async16(sbase + SM_A + ROWSWZ(m, c), src + (size_t)m * 256 + c * 16);
        }
    }
    {
        const char* src = (const char*)g_qw;
#pragma unroll
        for (int i = 0; i < 8; i++) {
            int f = tid + i * 256;
            int n = f >> 4, c = f & 15;
            cp_async16(sbase + SM_B0 + ROWSWZ(n, c), src + (size_t)n * 256 + c * 16);
        }
    }
    CP_COMMIT();
    CP_WAIT0();
    __syncthreads();

    float izv[4];
#pragma unroll
    for (int s = 0; s < 4; s++)
        izv[s] = sizs[wm * 32 + (s >> 1) * 16 + (s & 1) * 8 + (lane >> 2)];

    uint32_t aBase[2], aSwz[2];
#pragma unroll
    for (int mt = 0; mt < 2; mt++) {
        int ml = wm * 32 + mt * 16 + ((lj & 1) << 3) + lr;
        aBase[mt] = sbase + SM_A + (uint32_t)ml * 256;
        aSwz[mt]  = (uint32_t)(ml & 7);
    }
    uint32_t bBase[4], bSwz[4];
#pragma unroll
    for (int p = 0; p < 4; p++) {
        int nl = wn * 64 + p * 16 + ((lj >> 1) << 3) + lr;
        bBase[p] = (uint32_t)nl * 256;
        bSwz[p]  = (uint32_t)(nl & 7);
    }

    float bv[4][6];
    int   bi[4][6];
#pragma unroll
    for (int s = 0; s < 4; s++)
#pragma unroll
        for (int e = 0; e < 6; e++) { bv[s][e] = -3.4e38f; bi[s][e] = 0; }

#define TOP6_INS(S, VAL, IDX)                                              \
    if ((VAL) > bv[S][5]) {                                                \
        float _cv = (VAL); int _ci = (IDX);                                \
        _Pragma("unroll")                                                  \
        for (int _q = 0; _q < 6; _q++) {                                   \
            if (_cv > bv[S][_q]) {                                         \
                float _tv = bv[S][_q]; int _ti = bi[S][_q];                \
                bv[S][_q] = _cv; bi[S][_q] = _ci; _cv = _tv; _ci = _ti;    \
            }                                                              \
        }                                                                  \
    }

#define LOAD_AFRAG(ks, dst)                                                        \
    {                                                                              \
        uint32_t cA = (uint32_t)((ks) * 2 + (lj >> 1));                            \
        _Pragma("unroll")                                                          \
        for (int mt = 0; mt < 2; mt++) {                                           \
            uint32_t ad = aBase[mt] + ((((cA & 8) | ((cA ^ aSwz[mt]) & 7))) << 4); \
            LDSM_X4((dst)[mt][0], (dst)[mt][1], (dst)[mt][2], (dst)[mt][3], ad);   \
        }                                                                          \
    }
#define LOAD_BFRAG(ks, cur, dst)                                                   \
    {                                                                              \
        uint32_t cB = (uint32_t)((ks) * 2 + (lj & 1));                             \
        _Pragma("unroll")                                                          \
        for (int p = 0; p < 4; p++) {                                              \
            uint32_t bd = (cur) + bBase[p] +                                       \
                          ((((cB & 8) | ((cB ^ bSwz[p]) & 7))) << 4);              \
            LDSM_X4((dst)[2 * p][0], (dst)[2 * p][1],                              \
                    (dst)[2 * p + 1][0], (dst)[2 * p + 1][1], bd);                 \
        }                                                                          \
    }

    int buf = 0;
    for (int t = 0; t < 64; t++) {
        const uint32_t cur = sbase + (buf ? SM_B1 : SM_B0);
        if (t < 63) {
            const uint32_t nxt = sbase + (buf ? SM_B0 : SM_B1);
            const char* src = (const char*)g_qw + (size_t)(t + 1) * 128 * 256;
#pragma unroll
            for (int i = 0; i < 8; i++) {
                int f = tid + i * 256;
                int n = f >> 4, c = f & 15;
                cp_async16(nxt + ROWSWZ(n, c), src + (size_t)n * 256 + c * 16);
            }
            CP_COMMIT();
        }

        int C[2][8][4];
#pragma unroll
        for (int mt = 0; mt < 2; mt++)
#pragma unroll
            for (int f = 0; f < 8; f++)
#pragma unroll
                for (int e = 0; e < 4; e++) C[mt][f][e] = 0;

        // software-pipelined fragment double buffer
        uint32_t af[2][2][4];
        uint32_t bf[2][8][2];
        LOAD_AFRAG(0, af[0]);
        LOAD_BFRAG(0, cur, bf[0]);
#pragma unroll
        for (int ks = 0; ks < 8; ks++) {
            int cu = ks & 1, nx = cu ^ 1;
            if (ks < 7) {
                LOAD_AFRAG(ks + 1, af[nx]);
                LOAD_BFRAG(ks + 1, cur, bf[nx]);
            }
#pragma unroll
            for (int mt = 0; mt < 2; mt++)
#pragma unroll
                for (int f = 0; f < 8; f++)
                    IMMA16832(C[mt][f], af[cu][mt], bf[cu][f]);
        }

        // epilogue: s = izs * (Q * iws) - 0.5||w||^2 ; update top-6
        {
            int cbase = t * 128 + wn * 64 + 2 * (lane & 3);
#pragma unroll
            for (int f = 0; f < 8; f++) {
#pragma unroll
                for (int e = 0; e < 2; e++) {
                    int col = cbase + f * 8 + e;
                    float iw = siws[col];
                    float wv = swn[col];
#pragma unroll
                    for (int mt = 0; mt < 2; mt++) {
                        float s0 = __int2float_rn(C[mt][f][e])     * iw * izv[mt * 2 + 0] - wv;
                        float s1 = __int2float_rn(C[mt][f][2 + e]) * iw * izv[mt * 2 + 1] - wv;
                        TOP6_INS(mt * 2 + 0, s0, col);
                        TOP6_INS(mt * 2 + 1, s1, col);
                    }
                }
            }
        }

        if (t < 63) CP_WAIT0();
        __syncthreads();
        buf ^= 1;
    }

    // ---- cross-thread merge: 48 candidates/row -> top-16 ----
    float* MV = (float*)(smem + SM_MV);   // [128][48]
    int*   MI = (int*)  (smem + SM_MI);
#pragma unroll
    for (int s = 0; s < 4; s++) {
        int row = wm * 32 + (s >> 1) * 16 + (s & 1) * 8 + (lane >> 2);
        int col = wn * 24 + (lane & 3) * 6;
#pragma unroll
        for (int e = 0; e < 6; e++) {
            MV[row * 48 + col + e] = bv[s][e];
            MI[row * 48 + col + e] = bi[s][e];
        }
    }
    __syncthreads();

    if (tid < 128) {
        int row = tid;
        float tv[NCAND];
        int   ti[NCAND];
#pragma unroll
        for (int e = 0; e < NCAND; e++) { tv[e] = -3.4e38f; ti[e] = 0; }
#pragma unroll 4
        for (int k = 0; k < 48; k++) {
            float v  = MV[row * 48 + k];
            int   ix = MI[row * 48 + k];
            if (v > tv[NCAND - 1]) {
                float cv = v; int ci = ix;
#pragma unroll
                for (int q = 0; q < NCAND; q++) {
                    if (cv > tv[q]) {
                        float xv = tv[q]; int xi = ti[q];
                        tv[q] = cv; ti[q] = ci; cv = xv; ci = xi;
                    }
                }
            }
        }
        int m = m0 + row;
#pragma unroll
        for (int e = 0; e < NCAND; e++) g_cand[m][e] = ti[e];
        int fl = (tv[0] - tv[NCAND - 1] <= CERT_WINDOW) ? 1 : 0;
        g_flag[m] = fl;
        if (fl) {
            int p = atomicAdd(&g_flag_count, 1);
            g_flag_list[p] = m;
        }
    }
}

// ---------------------------------------------------------------------------
// 4) Exact fp32 rescore of top-16 candidates (one warp per row)
// ---------------------------------------------------------------------------
__global__ __launch_bounds__(256) void rescore_kernel(const float* __restrict__ zout,
                                                      const float* __restrict__ w,
                                                      float* __restrict__ idxf) {
    int m    = (blockIdx.x * blockDim.x + threadIdx.x) >> 5;
    int lane = threadIdx.x & 31;
    if (m >= Mn) return;
    if (g_flag[m]) return;

    float zr[8];
    const float* zp = zout + (size_t)m * Kn;
#pragma unroll
    for (int j = 0; j < 8; j++) zr[j] = zp[lane + 32 * j];

    float bestS = -3.4e38f;
    int   bestI = 0x7fffffff;
#pragma unroll 4
    for (int c = 0; c < NCAND; c++) {
        int idx = g_cand[m][c];
        const float* wp = w + (size_t)idx * Kn;
        float s = 0.f;
#pragma unroll
        for (int j = 0; j < 8; j++) s += zr[j] * wp[lane + 32 * j];
#pragma unroll
        for (int o = 16; o > 0; o >>= 1) s += __shfl_xor_sync(0xffffffffu, s, o);
        s -= g_wnorm[idx];
        if (s > bestS || (s == bestS && idx < bestI)) { bestS = s; bestI = idx; }
    }
    if (lane == 0) {
        g_bestidx[m] = bestI;
        idxf[m] = (float)bestI;
    }
}

// ---------------------------------------------------------------------------
// 5) Fallback full exact scan for flagged rows (expected ~0 rows)
// ---------------------------------------------------------------------------
__global__ __launch_bounds__(256) void fallback_kernel(const float* __restrict__ zout,
                                                       const float* __restrict__ w,
                                                       float* __restrict__ idxf) {
    __shared__ float sv[8];
    __shared__ int   si[8];
    int nflag = g_flag_count;
    int wi = threadIdx.x >> 5, lane = threadIdx.x & 31;
    for (int r = blockIdx.x; r < nflag; r += gridDim.x) {
        int m = g_flag_list[r];
        float zr[8];
        const float* zp = zout + (size_t)m * Kn;
#pragma unroll
        for (int j = 0; j < 8; j++) zr[j] = zp[lane + 32 * j];
        float bS = -3.4e38f;
        int   bI = 0x7fffffff;
        for (int n = wi; n < Nn; n += 8) {
            const float* wp = w + (size_t)n * Kn;
            float s = 0.f;
#pragma unroll
            for (int j = 0; j < 8; j++) s += zr[j] * wp[lane + 32 * j];
#pragma unroll
            for (int o = 16; o > 0; o >>= 1) s += __shfl_xor_sync(0xffffffffu, s, o);
            s -= g_wnorm[n];
            if (s > bS || (s == bS && n < bI)) { bS = s; bI = n; }
        }
        if (lane == 0) { sv[wi] = bS; si[wi] = bI; }
        __syncthreads();
        if (threadIdx.x == 0) {
            float bvv = sv[0]; int bii = si[0];
#pragma unroll
            for (int q = 1; q < 8; q++) {
                if (sv[q] > bvv || (sv[q] == bvv && si[q] < bii)) { bvv = sv[q]; bii = si[q]; }
            }
            g_bestidx[m] = bii;
            idxf[m] = (float)bii;
        }
        __syncthreads();
    }
}

// ---------------------------------------------------------------------------
// 6) Gather z_q
// ---------------------------------------------------------------------------
__global__ void gather_kernel(const float* __restrict__ w,
                              float* __restrict__ zq) {
    int t   = blockIdx.x * blockDim.x + threadIdx.x;
    int row = t >> 6;
    int c   = t & 63;
    int idx = g_bestidx[row];
    reinterpret_cast<float4*>(zq)[t] =
        reinterpret_cast<const float4*>(w)[(size_t)idx * 64 + c];
}

// ---------------------------------------------------------------------------
extern "C" void kernel_launch(void* const* d_in, const int* in_sizes, int n_in,
                              void* d_out, int out_size) {
    const float* z = (const float*)d_in[0];
    const float* w = (const float*)d_in[1];
    float* out   = (float*)d_out;
    float* z_out = out;
    float* z_q   = out + OUT_ZQ;
    float* idxf  = out + OUT_IDX;

    cudaFuncSetAttribute(gemm_kernel,
                         cudaFuncAttributeMaxDynamicSharedMemorySize, SMEM_BYTES);

    dim3 tt(32, 8);
    transpose_kernel<<<dim3(HWn / 32, Kn / 32, Bln), tt>>>(z, z_out);
    zquant_kernel<<<Mn / 8, 256>>>(z_out);
    wquant_kernel<<<Nn / 8, 256>>>(w);
    gemm_kernel<<<Mn / 128, 256, SMEM_BYTES>>>();
    rescore_kernel<<<Mn / 8, 256>>>(z_out, w, idxf);
    fallback_kernel<<<128, 256>>>(z_out, w, idxf);
    gather_kernel<<<(Mn * Kn / 4) / 256, 256>>>(w, z_q);
}

// round 7
// speedup vs baseline: 4.3770x; 1.1763x over previous
#include <cuda_runtime.h>
#include <cuda_bf16.h>
#include <cstdint>

// ---------------------------------------------------------------------------
#define Mn  16384
#define Nn  8192
#define Kn  256
#define HWn 1024
#define Bln 16

#define OUT_ZQ  (Mn * Kn)
#define OUT_IDX (2 * Mn * Kn)

#define CERT_WINDOW 3.5f
#define NCAND 16

// ---------------------------------------------------------------------------
__device__ __align__(16) int8_t g_qz[Mn * Kn];
__device__ __align__(16) int8_t g_qw[Nn * Kn];
__device__ float g_izs[Mn];
__device__ float g_iws[Nn];
__device__ float g_wnorm[Nn];
__device__ int   g_bestidx[Mn];
__device__ int   g_cand[Mn][NCAND];
__device__ int   g_flag[Mn];
__device__ int   g_flag_list[Mn];
__device__ int   g_flag_count;

// ---------------------------------------------------------------------------
__device__ __forceinline__ uint32_t smem_u32(const void* p) {
    uint32_t a;
    asm("{ .reg .u64 t; cvta.to.shared.u64 t, %1; cvt.u32.u64 %0, t; }"
        : "=r"(a) : "l"(p));
    return a;
}
__device__ __forceinline__ void cp_async16(uint32_t dst, const void* src) {
    asm volatile("cp.async.cg.shared.global [%0], [%1], 16;"
                 :: "r"(dst), "l"(src) : "memory");
}
#define CP_COMMIT() asm volatile("cp.async.commit_group;" ::: "memory")
#define CP_WAIT0()  asm volatile("cp.async.wait_group 0;" ::: "memory")

#define LDSM_X4(r0, r1, r2, r3, a) \
    asm volatile("ldmatrix.sync.aligned.m8n8.x4.shared.b16 {%0,%1,%2,%3}, [%4];" \
                 : "=r"(r0), "=r"(r1), "=r"(r2), "=r"(r3) : "r"(a))

#define IMMA16832(c, a, b) \
    asm volatile("mma.sync.aligned.m16n8k32.row.col.s32.s8.s8.s32 " \
                 "{%0,%1,%2,%3}, {%4,%5,%6,%7}, {%8,%9}, {%0,%1,%2,%3};" \
                 : "+r"((c)[0]), "+r"((c)[1]), "+r"((c)[2]), "+r"((c)[3]) \
                 : "r"((a)[0]), "r"((a)[1]), "r"((a)[2]), "r"((a)[3]), \
                   "r"((b)[0]), "r"((b)[1]))

// ---------------------------------------------------------------------------
// 1) Transpose: z [B,C,HW] -> z_out fp32 [B,HW,C]
// ---------------------------------------------------------------------------
__global__ void transpose_kernel(const float* __restrict__ z,
                                 float* __restrict__ zout) {
    __shared__ float tile[32][33];
    int b   = blockIdx.z;
    int hw0 = blockIdx.x * 32;
    int c0  = blockIdx.y * 32;
    const float* zp = z + (size_t)b * (Kn * HWn);
    size_t obase    = (size_t)b * (Kn * HWn);
    int tx = threadIdx.x, ty = threadIdx.y;
#pragma unroll
    for (int j = 0; j < 32; j += 8)
        tile[ty + j][tx] = zp[(c0 + ty + j) * HWn + hw0 + tx];
    __syncthreads();
#pragma unroll
    for (int j = 0; j < 32; j += 8)
        zout[obase + (size_t)(hw0 + ty + j) * Kn + c0 + tx] = tile[tx][ty + j];
}

// ---------------------------------------------------------------------------
// 2a) z row quantization
// ---------------------------------------------------------------------------
__global__ __launch_bounds__(256) void zquant_kernel(const float* __restrict__ zout) {
    int row  = (blockIdx.x * blockDim.x + threadIdx.x) >> 5;
    int lane = threadIdx.x & 31;
    const float4* zp = (const float4*)(zout + (size_t)row * Kn) + lane * 2;
    float4 v0 = zp[0], v1 = zp[1];
    float vals[8] = {v0.x, v0.y, v0.z, v0.w, v1.x, v1.y, v1.z, v1.w};
    float mx = 0.f;
#pragma unroll
    for (int j = 0; j < 8; j++) mx = fmaxf(mx, fabsf(vals[j]));
#pragma unroll
    for (int o = 16; o > 0; o >>= 1) mx = fmaxf(mx, __shfl_xor_sync(0xffffffffu, mx, o));
    mx = fmaxf(mx, 1e-20f);
    float zs = 127.f / mx;
    uint32_t p0 = 0, p1 = 0;
#pragma unroll
    for (int j = 0; j < 4; j++) {
        p0 |= ((uint32_t)(__float2int_rn(vals[j] * zs)     & 0xff)) << (8 * j);
        p1 |= ((uint32_t)(__float2int_rn(vals[4 + j] * zs) & 0xff)) << (8 * j);
    }
    *(uint2*)(g_qz + (size_t)row * Kn + lane * 8) = make_uint2(p0, p1);
    if (lane == 0) g_izs[row] = mx / 127.f;
}

// ---------------------------------------------------------------------------
// 2b) w row quantization + wnorm
// ---------------------------------------------------------------------------
__global__ __launch_bounds__(256) void wquant_kernel(const float* __restrict__ w) {
    if (blockIdx.x == 0 && threadIdx.x == 0) g_flag_count = 0;
    int row  = (blockIdx.x * blockDim.x + threadIdx.x) >> 5;
    int lane = threadIdx.x & 31;
    if (row >= Nn) return;
    const float4* wp = (const float4*)(w + (size_t)row * Kn) + lane * 2;
    float4 v0 = wp[0], v1 = wp[1];
    float vals[8] = {v0.x, v0.y, v0.z, v0.w, v1.x, v1.y, v1.z, v1.w};
    float mx = 0.f, ss = 0.f;
#pragma unroll
    for (int j = 0; j < 8; j++) { mx = fmaxf(mx, fabsf(vals[j])); ss += vals[j] * vals[j]; }
#pragma unroll
    for (int o = 16; o > 0; o >>= 1) {
        mx = fmaxf(mx, __shfl_xor_sync(0xffffffffu, mx, o));
        ss += __shfl_xor_sync(0xffffffffu, ss, o);
    }
    mx = fmaxf(mx, 1e-20f);
    float ws = 127.f / mx;
    uint32_t p0 = 0, p1 = 0;
#pragma unroll
    for (int j = 0; j < 4; j++) {
        p0 |= ((uint32_t)(__float2int_rn(vals[j] * ws)     & 0xff)) << (8 * j);
        p1 |= ((uint32_t)(__float2int_rn(vals[4 + j] * ws) & 0xff)) << (8 * j);
    }
    *(uint2*)(g_qw + (size_t)row * Kn + lane * 8) = make_uint2(p0, p1);
    if (lane == 0) {
        g_iws[row]   = mx / 127.f;
        g_wnorm[row] = 0.5f * ss;
    }
}

// ---------------------------------------------------------------------------
// 3) int8 IMMA GEMM, BM=64, 2 CTAs/SM for MMA/epilogue overlap
//    8 warps: 2(m) x 4(n), warp tile 32x32, K=256 resident
// ---------------------------------------------------------------------------
#define SM_A    0          // 16 KB
#define SM_B0   16384      // 32 KB
#define SM_B1   49152      // 32 KB
#define SMEM_BYTES 81920
#define SM_MV   0          // merge pool (post-loop)
#define SM_MI   24576

#define ROWSWZ(m, c) ((uint32_t)((m) * 256 + ((((c) & 8) | (((c) ^ ((m) & 7)) & 7)) << 4)))

__global__ void __launch_bounds__(256, 2) gemm_kernel() {
    extern __shared__ char smem[];
    const uint32_t sbase = smem_u32(smem);
    const int tid  = threadIdx.x;
    const int lane = tid & 31;
    const int wid  = tid >> 5;
    const int wm   = wid >> 2;     // 0..1
    const int wn   = wid & 3;      // 0..3
    const int lj   = lane >> 3;
    const int lr   = lane & 7;
    const int m0   = blockIdx.x * 64;

    // A tile (64 x 256 s8): 1024 16B chunks, 4 per thread
    {
        const char* src = (const char*)g_qz + (size_t)m0 * 256;
#pragma unroll
        for (int i = 0; i < 4; i++) {
            int f = tid + i * 256;
            int m = f >> 4, c = f & 15;
            cp_async16(sbase + SM_A + ROWSWZ(m, c), src + (size_t)m * 256 + c * 16);
        }
    }
    // B tile 0 (128 x 256 s8): 2048 chunks, 8 per thread
    {
        const char* src = (const char*)g_qw;
#pragma unroll
        for (int i = 0; i < 8; i++) {
            int f = tid + i * 256;
            int n = f >> 4, c = f & 15;
            cp_async16(sbase + SM_B0 + ROWSWZ(n, c), src + (size_t)n * 256 + c * 16);
        }
    }
    CP_COMMIT();

    // per-slot inverse z scale (slot s: row = wm*32 + (s>>1)*16 + (s&1)*8 + lane/4)
    float izv[4];
#pragma unroll
    for (int s = 0; s < 4; s++)
        izv[s] = __ldg(&g_izs[m0 + wm * 32 + (s >> 1) * 16 + (s & 1) * 8 + (lane >> 2)]);

    CP_WAIT0();
    __syncthreads();

    uint32_t aBase[2], aSwz[2];
#pragma unroll
    for (int mt = 0; mt < 2; mt++) {
        int ml = wm * 32 + mt * 16 + ((lj & 1) << 3) + lr;
        aBase[mt] = sbase + SM_A + (uint32_t)ml * 256;
        aSwz[mt]  = (uint32_t)(ml & 7);
    }
    uint32_t bBase[2], bSwz[2];
#pragma unroll
    for (int p = 0; p < 2; p++) {
        int nl = wn * 32 + p * 16 + ((lj >> 1) << 3) + lr;
        bBase[p] = (uint32_t)nl * 256;
        bSwz[p]  = (uint32_t)(nl & 7);
    }

    float bv[4][6];
    int   bi[4][6];
#pragma unroll
    for (int s = 0; s < 4; s++)
#pragma unroll
        for (int e = 0; e < 6; e++) { bv[s][e] = -3.4e38f; bi[s][e] = 0; }

#define TOP6_INS(S, VAL, IDX)                                              \
    if ((VAL) > bv[S][5]) {                                                \
        float _cv = (VAL); int _ci = (IDX);                                \
        _Pragma("unroll")                                                  \
        for (int _q = 0; _q < 6; _q++) {                                   \
            if (_cv > bv[S][_q]) {                                         \
                float _tv = bv[S][_q]; int _ti = bi[S][_q];                \
                bv[S][_q] = _cv; bi[S][_q] = _ci; _cv = _tv; _ci = _ti;    \
            }                                                              \
        }                                                                  \
    }

    int buf = 0;
    for (int t = 0; t < 64; t++) {
        const uint32_t cur = sbase + (buf ? SM_B1 : SM_B0);
        if (t < 63) {
            const uint32_t nxt = sbase + (buf ? SM_B0 : SM_B1);
            const char* src = (const char*)g_qw + (size_t)(t + 1) * 128 * 256;
#pragma unroll
            for (int i = 0; i < 8; i++) {
                int f = tid + i * 256;
                int n = f >> 4, c = f & 15;
                cp_async16(nxt + ROWSWZ(n, c), src + (size_t)n * 256 + c * 16);
            }
            CP_COMMIT();
        }

        // prefetch epilogue constants (hidden under MMA phase)
        const int cbase = t * 128 + wn * 32 + 2 * (lane & 3);
        float wv[4][2], iw[4][2];
#pragma unroll
        for (int f = 0; f < 4; f++) {
#pragma unroll
            for (int e = 0; e < 2; e++) {
                wv[f][e] = __ldg(&g_wnorm[cbase + f * 8 + e]);
                iw[f][e] = __ldg(&g_iws[cbase + f * 8 + e]);
            }
        }

        int C[2][4][4];
#pragma unroll
        for (int mt = 0; mt < 2; mt++)
#pragma unroll
            for (int f = 0; f < 4; f++)
#pragma unroll
                for (int e = 0; e < 4; e++) C[mt][f][e] = 0;

#pragma unroll
        for (int ks = 0; ks < 8; ks++) {
            uint32_t a[2][4];
            uint32_t cA = (uint32_t)(ks * 2 + (lj >> 1));
#pragma unroll
            for (int mt = 0; mt < 2; mt++) {
                uint32_t ad = aBase[mt] + ((((cA & 8) | ((cA ^ aSwz[mt]) & 7))) << 4);
                LDSM_X4(a[mt][0], a[mt][1], a[mt][2], a[mt][3], ad);
            }
            uint32_t b[4][2];
            uint32_t cB = (uint32_t)(ks * 2 + (lj & 1));
#pragma unroll
            for (int p = 0; p < 2; p++) {
                uint32_t bd = cur + bBase[p] + ((((cB & 8) | ((cB ^ bSwz[p]) & 7))) << 4);
                LDSM_X4(b[2 * p][0], b[2 * p][1], b[2 * p + 1][0], b[2 * p + 1][1], bd);
            }
#pragma unroll
            for (int mt = 0; mt < 2; mt++)
#pragma unroll
                for (int f = 0; f < 4; f++)
                    IMMA16832(C[mt][f], a[mt], b[f]);
        }

        // epilogue: s = izs * (Q * iws) - 0.5||w||^2 ; update top-6
#pragma unroll
        for (int f = 0; f < 4; f++) {
#pragma unroll
            for (int e = 0; e < 2; e++) {
                int col = cbase + f * 8 + e;
#pragma unroll
                for (int mt = 0; mt < 2; mt++) {
                    float s0 = __int2float_rn(C[mt][f][e])     * iw[f][e] * izv[mt * 2 + 0] - wv[f][e];
                    float s1 = __int2float_rn(C[mt][f][2 + e]) * iw[f][e] * izv[mt * 2 + 1] - wv[f][e];
                    TOP6_INS(mt * 2 + 0, s0, col);
                    TOP6_INS(mt * 2 + 1, s1, col);
                }
            }
        }

        if (t < 63) CP_WAIT0();
        __syncthreads();
        buf ^= 1;
    }

    // ---- cross-thread merge: 96 candidates/row -> top-16 ----
    float* MV = (float*)(smem + SM_MV);   // [64][96]
    int*   MI = (int*)  (smem + SM_MI);
#pragma unroll
    for (int s = 0; s < 4; s++) {
        int row = wm * 32 + (s >> 1) * 16 + (s & 1) * 8 + (lane >> 2);
        int col = (wn * 4 + (lane & 3)) * 6;
#pragma unroll
        for (int e = 0; e < 6; e++) {
            MV[row * 96 + col + e] = bv[s][e];
            MI[row * 96 + col + e] = bi[s][e];
        }
    }
    __syncthreads();

    if (tid < 64) {
        int row = tid;
        float tv[NCAND];
        int   ti[NCAND];
#pragma unroll
        for (int e = 0; e < NCAND; e++) { tv[e] = -3.4e38f; ti[e] = 0; }
        for (int k = 0; k < 96; k++) {
            float v  = MV[row * 96 + k];
            int   ix = MI[row * 96 + k];
            if (v > tv[NCAND - 1]) {
                float cv = v; int ci = ix;
#pragma unroll
                for (int q = 0; q < NCAND; q++) {
                    if (cv > tv[q]) {
                        float xv = tv[q]; int xi = ti[q];
                        tv[q] = cv; ti[q] = ci; cv = xv; ci = xi;
                    }
                }
            }
        }
        int m = m0 + row;
#pragma unroll
        for (int e = 0; e < NCAND; e++) g_cand[m][e] = ti[e];
        int fl = (tv[0] - tv[NCAND - 1] <= CERT_WINDOW) ? 1 : 0;
        g_flag[m] = fl;
        if (fl) {
            int p = atomicAdd(&g_flag_count, 1);
            g_flag_list[p] = m;
        }
    }
}

// ---------------------------------------------------------------------------
// 4) Exact fp32 rescore of top-16 candidates (one warp per row)
// ---------------------------------------------------------------------------
__global__ __launch_bounds__(256) void rescore_kernel(const float* __restrict__ zout,
                                                      const float* __restrict__ w,
                                                      float* __restrict__ idxf) {
    int m    = (blockIdx.x * blockDim.x + threadIdx.x) >> 5;
    int lane = threadIdx.x & 31;
    if (m >= Mn) return;
    if (g_flag[m]) return;

    float zr[8];
    const float* zp = zout + (size_t)m * Kn;
#pragma unroll
    for (int j = 0; j < 8; j++) zr[j] = zp[lane + 32 * j];

    float bestS = -3.4e38f;
    int   bestI = 0x7fffffff;
#pragma unroll 4
    for (int c = 0; c < NCAND; c++) {
        int idx = g_cand[m][c];
        const float* wp = w + (size_t)idx * Kn;
        float s = 0.f;
#pragma unroll
        for (int j = 0; j < 8; j++) s += zr[j] * wp[lane + 32 * j];
#pragma unroll
        for (int o = 16; o > 0; o >>= 1) s += __shfl_xor_sync(0xffffffffu, s, o);
        s -= g_wnorm[idx];
        if (s > bestS || (s == bestS && idx < bestI)) { bestS = s; bestI = idx; }
    }
    if (lane == 0) {
        g_bestidx[m] = bestI;
        idxf[m] = (float)bestI;
    }
}

// ---------------------------------------------------------------------------
// 5) Fallback full exact scan for flagged rows (expected ~0 rows)
// ---------------------------------------------------------------------------
__global__ __launch_bounds__(256) void fallback_kernel(const float* __restrict__ zout,
                                                       const float* __restrict__ w,
                                                       float* __restrict__ idxf) {
    __shared__ float sv[8];
    __shared__ int   si[8];
    int nflag = g_flag_count;
    int wi = threadIdx.x >> 5, lane = threadIdx.x & 31;
    for (int r = blockIdx.x; r < nflag; r += gridDim.x) {
        int m = g_flag_list[r];
        float zr[8];
        const float* zp = zout + (size_t)m * Kn;
#pragma unroll
        for (int j = 0; j < 8; j++) zr[j] = zp[lane + 32 * j];
        float bS = -3.4e38f;
        int   bI = 0x7fffffff;
        for (int n = wi; n < Nn; n += 8) {
            const float* wp = w + (size_t)n * Kn;
            float s = 0.f;
#pragma unroll
            for (int j = 0; j < 8; j++) s += zr[j] * wp[lane + 32 * j];
#pragma unroll
            for (int o = 16; o > 0; o >>= 1) s += __shfl_xor_sync(0xffffffffu, s, o);
            s -= g_wnorm[n];
            if (s > bS || (s == bS && n < bI)) { bS = s; bI = n; }
        }
        if (lane == 0) { sv[wi] = bS; si[wi] = bI; }
        __syncthreads();
        if (threadIdx.x == 0) {
            float bvv = sv[0]; int bii = si[0];
#pragma unroll
            for (int q = 1; q < 8; q++) {
                if (sv[q] > bvv || (sv[q] == bvv && si[q] < bii)) { bvv = sv[q]; bii = si[q]; }
            }
            g_bestidx[m] = bii;
            idxf[m] = (float)bii;
        }
        __syncthreads();
    }
}

// ---------------------------------------------------------------------------
// 6) Gather z_q
// ---------------------------------------------------------------------------
__global__ void gather_kernel(const float* __restrict__ w,
                              float* __restrict__ zq) {
    int t   = blockIdx.x * blockDim.x + threadIdx.x;
    int row = t >> 6;
    int c   = t & 63;
    int idx = g_bestidx[row];
    reinterpret_cast<float4*>(zq)[t] =
        reinterpret_cast<const float4*>(w)[(size_t)idx * 64 + c];
}

// ---------------------------------------------------------------------------
extern "C" void kernel_launch(void* const* d_in, const int* in_sizes, int n_in,
                              void* d_out, int out_size) {
    const float* z = (const float*)d_in[0];
    const float* w = (const float*)d_in[1];
    float* out   = (float*)d_out;
    float* z_out = out;
    float* z_q   = out + OUT_ZQ;
    float* idxf  = out + OUT_IDX;

    cudaFuncSetAttribute(gemm_kernel,
                         cudaFuncAttributeMaxDynamicSharedMemorySize, SMEM_BYTES);

    dim3 tt(32, 8);
    transpose_kernel<<<dim3(HWn / 32, Kn / 32, Bln), tt>>>(z, z_out);
    zquant_kernel<<<Mn / 8, 256>>>(z_out);
    wquant_kernel<<<Nn / 8, 256>>>(w);
    gemm_kernel<<<Mn / 64, 256, SMEM_BYTES>>>();
    rescore_kernel<<<Mn / 8, 256>>>(z_out, w, idxf);
    fallback_kernel<<<128, 256>>>(z_out, w, idxf);
    gather_kernel<<<(Mn * Kn / 4) / 256, 256>>>(w, z_q);
}